// round 4
// baseline (speedup 1.0000x reference)
#include <cuda_runtime.h>
#include <cuda_bf16.h>

#define GS 32
#define NN 16
#define SLICES 4
#define ATOM_TYPE 6

// out[b,a,i,j,k] = sum_{n: an[a,n]==6} exp(coeff*||grid - dv||^2), separable.
// Barrier-free, shared-free: every thread computes its own factors in registers.
// Block = (ba, group of 4 i-slices), 256 threads.
// Thread t owns (j = t>>3, k0 = (t&7)*4) across 4 i-slices -> 16 outputs.
__global__ __launch_bounds__(256) void voxel_kernel(
    const float* __restrict__ dv,     // (B, A, N, 3)
    const int*   __restrict__ an,     // (A, N) int32
    const float* __restrict__ sigma,  // (1,)
    float* __restrict__ out)          // (B, A, G, G, G)
{
    const int ba = blockIdx.x;        // b*32 + a
    const int a  = ba & 31;
    const int iq = blockIdx.y;        // slices [iq*4, iq*4+4)
    const int t  = threadIdx.x;
    const int j  = t >> 3;
    const int k0 = (t & 7) << 2;
    const int lane = t & 31;

    // Prefetch this block's dv rows and sigma concurrently with the an load,
    // so the per-neighbor dv reads below are L1 hits.
    float pf = 0.0f;
    if (t < NN * 3) pf = dv[(long)ba * (NN * 3) + t];
    asm volatile("" :: "f"(pf));
    const float sg = __ldg(sigma);

    // Per-warp ballot compaction (warp-uniform mask, no shared, no barrier).
    bool act = false;
    if (lane < NN) act = (an[a * NN + lane] == ATOM_TYPE);
    unsigned mask = __ballot_sync(0xffffffffu, act);

    const float coeff = -0.5f / (sg * sg);
    const float step = 8.0f / 31.0f;

    const float tj = -4.0f + (float)j * step;
    float tk[4], ti[SLICES];
    #pragma unroll
    for (int k = 0; k < 4; ++k) tk[k] = -4.0f + (float)(k0 + k) * step;
    #pragma unroll
    for (int ii = 0; ii < SLICES; ++ii)
        ti[ii] = -4.0f + (float)(iq * SLICES + ii) * step;

    float4 acc[SLICES];
    #pragma unroll
    for (int ii = 0; ii < SLICES; ++ii) acc[ii] = make_float4(0.f, 0.f, 0.f, 0.f);

    // Iterate active neighbors straight off the ballot mask.
    while (mask) {
        const int n = __ffs(mask) - 1;
        mask &= mask - 1;

        const float* p = dv + ((long)ba * NN + n) * 3;   // L1 hit (prefetched)
        const float dx = p[0], dy = p[1], dz = p[2];

        // Merged y*z factor: exp(coeff*ddy^2 + coeff*ddz_k^2)  -> 4 exps
        const float ddy  = tj - dy;
        const float argy = coeff * ddy * ddy;
        float eyz[4];
        #pragma unroll
        for (int k = 0; k < 4; ++k) {
            const float ddz = tk[k] - dz;
            eyz[k] = __expf(fmaf(coeff * ddz, ddz, argy));
        }

        // x factor per slice -> 4 exps
        float ex[SLICES];
        #pragma unroll
        for (int ii = 0; ii < SLICES; ++ii) {
            const float ddx = ti[ii] - dx;
            ex[ii] = __expf(coeff * ddx * ddx);
        }

        #pragma unroll
        for (int ii = 0; ii < SLICES; ++ii) {
            acc[ii].x = fmaf(ex[ii], eyz[0], acc[ii].x);
            acc[ii].y = fmaf(ex[ii], eyz[1], acc[ii].y);
            acc[ii].z = fmaf(ex[ii], eyz[2], acc[ii].z);
            acc[ii].w = fmaf(ex[ii], eyz[3], acc[ii].w);
        }
    }

    float* outp = out + (long)ba * (GS * GS * GS)
                      + (long)(iq * SLICES) * (GS * GS)
                      + 4 * t;   // j*32 + k0 == 4*t
    #pragma unroll
    for (int ii = 0; ii < SLICES; ++ii)
        *reinterpret_cast<float4*>(outp + ii * (GS * GS)) = acc[ii];
}

extern "C" void kernel_launch(void* const* d_in, const int* in_sizes, int n_in,
                              void* d_out, int out_size) {
    const float* dv    = (const float*)d_in[0];   // distance_vector (B,32,16,3)
    const int*   an    = (const int*)d_in[1];     // atomic_numbers (32,16) int32
    const float* sigma = (const float*)d_in[2];   // (1,)
    float* out = (float*)d_out;

    const int B = in_sizes[0] / (32 * 16 * 3);    // derive batch from input size
    dim3 grid(B * 32, GS / SLICES);               // (128, 8) = 1024 blocks
    voxel_kernel<<<grid, 256>>>(dv, an, sigma, out);
}